// round 1
// baseline (speedup 1.0000x reference)
#include <cuda_runtime.h>
#include <cstdint>
#include <cstddef>

// Problem constants
#define BATCH   4
#define NHEAD   12
#define DH      64
#define HID     768
#define HDIM    32
#define WDIM    32
#define NTOK    1024            // HDIM*WDIM
#define BH      48              // BATCH*NHEAD
#define MTOK    4096            // BATCH*NTOK

// ---------------- scratch (device globals; no runtime allocation) -------------
__device__ float g_q   [(size_t)BH * NTOK * DH];     // (bh, tok, d)
__device__ float g_k   [(size_t)BH * NTOK * DH];     // (bh, tok, d)
__device__ float g_kT  [(size_t)BH * DH * NTOK];     // (bh, d, tok)
__device__ float g_v   [(size_t)BH * NTOK * DH];     // (bh, tok, d)
__device__ float g_relh[(size_t)BH * NTOK * 32];     // (bh, tok, kh)
__device__ float g_relw[(size_t)BH * NTOK * 32];     // (bh, tok, kw)
__device__ float g_attn[(size_t)BH * NTOK * NTOK];   // (bh, tok, m)  ~201MB
__device__ float g_o   [(size_t)MTOK * HID];         // (b*1024+tok, h*64+d)

// ---------------- shared 64x64x16 GEMM core (256 threads, 4x4 micro) ----------
// C_tile[64x64] = A[m0:m0+64, :K] (lda) * B[:K, n0:n0+64] (ldb), fp32.
__device__ __forceinline__ void gemm64_core(
    const float* __restrict__ A, int lda,
    const float* __restrict__ B, int ldb,
    int K, int m0, int n0, float acc[4][4])
{
    __shared__ float As[16][64];   // [k][m] (transposed on store)
    __shared__ float Bs[16][68];   // [k][n] padded

    const int tid = threadIdx.x;
    const int tx  = tid & 15;
    const int ty  = tid >> 4;
    const int ra  = tid >> 2;             // A row 0..63
    const int qa  = (tid & 3) << 2;       // A k-chunk 0,4,8,12
    const int krb = tid >> 4;             // B k-row 0..15
    const int qb  = (tid & 15) << 2;      // B col chunk

    for (int k0 = 0; k0 < K; k0 += 16) {
        float4 va = *reinterpret_cast<const float4*>(
            A + (size_t)(m0 + ra) * lda + k0 + qa);
        float4 vb = *reinterpret_cast<const float4*>(
            B + (size_t)(k0 + krb) * ldb + n0 + qb);
        As[qa + 0][ra] = va.x;
        As[qa + 1][ra] = va.y;
        As[qa + 2][ra] = va.z;
        As[qa + 3][ra] = va.w;
        *reinterpret_cast<float4*>(&Bs[krb][qb]) = vb;
        __syncthreads();
        #pragma unroll
        for (int kk = 0; kk < 16; ++kk) {
            float4 a4 = *reinterpret_cast<const float4*>(&As[kk][ty << 2]);
            float4 b4 = *reinterpret_cast<const float4*>(&Bs[kk][tx << 2]);
            float a[4] = {a4.x, a4.y, a4.z, a4.w};
            float b[4] = {b4.x, b4.y, b4.z, b4.w};
            #pragma unroll
            for (int i = 0; i < 4; ++i)
                #pragma unroll
                for (int j = 0; j < 4; ++j)
                    acc[i][j] = fmaf(a[i], b[j], acc[i][j]);
        }
        __syncthreads();
    }
}

// ---------------- 1) qkv = x @ w_qkv, scattered into g_q/g_k/g_v --------------
__global__ __launch_bounds__(256) void k_gemm_qkv(
    const float* __restrict__ x, const float* __restrict__ w)
{
    const int m0 = blockIdx.y * 64;
    const int n0 = blockIdx.x * 64;            // tile never straddles sel/head
    float acc[4][4] = {};
    gemm64_core(x, HID, w, 3 * NHEAD * DH, HID, m0, n0, acc);

    const int tx = threadIdx.x & 15;
    const int ty = threadIdx.x >> 4;
    const int sel  = n0 / (NHEAD * DH);
    const int head = (n0 % (NHEAD * DH)) >> 6;
    float* dst = (sel == 0) ? g_q : (sel == 1) ? g_k : g_v;

    #pragma unroll
    for (int i = 0; i < 4; ++i) {
        const int m = m0 + (ty << 2) + i;
        const int b = m >> 10;
        const int tok = m & 1023;
        float4 v4 = make_float4(acc[i][0], acc[i][1], acc[i][2], acc[i][3]);
        *reinterpret_cast<float4*>(
            &dst[(((size_t)(b * NHEAD + head) * NTOK + tok) << 6) + (tx << 2)]) = v4;
    }
}

// ---------------- 2) transpose K: (bh,tok,d) -> (bh,d,tok) ---------------------
__global__ __launch_bounds__(256) void k_transpose()
{
    __shared__ float t[32][33];
    const int bh   = blockIdx.z;
    const int tok0 = blockIdx.x * 32;
    const int d0   = blockIdx.y * 32;
    const int x  = threadIdx.x;   // 0..31
    const int y0 = threadIdx.y;   // 0..7
    const float* src = g_k  + ((size_t)bh << 16);
    float*       dst = g_kT + ((size_t)bh << 16);
    #pragma unroll
    for (int yy = 0; yy < 32; yy += 8)
        t[y0 + yy][x] = src[(size_t)(tok0 + y0 + yy) * DH + d0 + x];
    __syncthreads();
    #pragma unroll
    for (int yy = 0; yy < 32; yy += 8)
        dst[(size_t)(d0 + y0 + yy) * NTOK + tok0 + x] = t[x][y0 + yy];
}

// ---------------- 3) rel_h / rel_w tables --------------------------------------
__global__ __launch_bounds__(64) void k_rel(
    const float* __restrict__ rel_pos_h, const float* __restrict__ rel_pos_w)
{
    const int bh  = blockIdx.y;
    const int tok = blockIdx.x;
    __shared__ float qs[64];
    const int t = threadIdx.x;
    qs[t] = g_q[(((size_t)bh << 10) + tok) * DH + t];
    __syncthreads();

    const int qh = tok >> 5;
    const int qw = tok & 31;
    const float* rp;
    float* out;
    int ridx;
    if (t < 32) {
        rp = rel_pos_h; ridx = qh - t + (HDIM - 1);
        out = &g_relh[(((size_t)bh << 10) + tok) * 32 + t];
    } else {
        const int kw = t - 32;
        rp = rel_pos_w; ridx = qw - kw + (WDIM - 1);
        out = &g_relw[(((size_t)bh << 10) + tok) * 32 + kw];
    }
    const float* r = rp + (size_t)ridx * DH;
    float s = 0.f;
    #pragma unroll
    for (int c = 0; c < 64; ++c) s = fmaf(qs[c], r[c], s);
    *out = s;
}

// ---------------- 4) logits = scale*Q@K^T + rel_h + rel_w ----------------------
__global__ __launch_bounds__(256) void k_logits()
{
    const int bh = blockIdx.z;
    const int m0 = blockIdx.y * 64;
    const int n0 = blockIdx.x * 64;
    const float* A = g_q  + ((size_t)bh << 16);   // 1024x64
    const float* B = g_kT + ((size_t)bh << 16);   // 64x1024
    float acc[4][4] = {};
    gemm64_core(A, DH, B, NTOK, DH, m0, n0, acc);

    const int tx = threadIdx.x & 15;
    const int ty = threadIdx.x >> 4;
    const float scale = 0.125f;                   // dh^-0.5
    const int col0 = n0 + (tx << 2);
    const int kh   = col0 >> 5;                   // constant over the 4 cols
    const int kw0  = col0 & 31;
    float* outb = g_attn + ((size_t)bh << 20);

    #pragma unroll
    for (int i = 0; i < 4; ++i) {
        const int tok = m0 + (ty << 2) + i;
        const float* rh = g_relh + (((size_t)bh << 10) + tok) * 32;
        const float* rw = g_relw + (((size_t)bh << 10) + tok) * 32;
        const float bh_bias = rh[kh];
        float4 v;
        v.x = fmaf(acc[i][0], scale, bh_bias + rw[kw0 + 0]);
        v.y = fmaf(acc[i][1], scale, bh_bias + rw[kw0 + 1]);
        v.z = fmaf(acc[i][2], scale, bh_bias + rw[kw0 + 2]);
        v.w = fmaf(acc[i][3], scale, bh_bias + rw[kw0 + 3]);
        *reinterpret_cast<float4*>(&outb[(size_t)tok * NTOK + col0]) = v;
    }
}

// ---------------- 5) softmax over rows of g_attn -------------------------------
__global__ __launch_bounds__(256) void k_softmax()
{
    const size_t row = blockIdx.x;                // 0..49151
    float* p = g_attn + (row << 10);
    const int t = threadIdx.x;
    float4 v = *reinterpret_cast<const float4*>(&p[t << 2]);

    float m = fmaxf(fmaxf(v.x, v.y), fmaxf(v.z, v.w));
    #pragma unroll
    for (int o = 16; o > 0; o >>= 1)
        m = fmaxf(m, __shfl_xor_sync(0xffffffffu, m, o));

    __shared__ float smax[8];
    __shared__ float ssum[8];
    const int w = t >> 5, lane = t & 31;
    if (lane == 0) smax[w] = m;
    __syncthreads();
    float M = smax[0];
    #pragma unroll
    for (int k = 1; k < 8; ++k) M = fmaxf(M, smax[k]);

    float e0 = __expf(v.x - M);
    float e1 = __expf(v.y - M);
    float e2 = __expf(v.z - M);
    float e3 = __expf(v.w - M);
    float s = e0 + e1 + e2 + e3;
    #pragma unroll
    for (int o = 16; o > 0; o >>= 1)
        s += __shfl_xor_sync(0xffffffffu, s, o);
    if (lane == 0) ssum[w] = s;
    __syncthreads();
    float S = ssum[0];
    #pragma unroll
    for (int k = 1; k < 8; ++k) S += ssum[k];
    const float inv = 1.0f / S;

    *reinterpret_cast<float4*>(&p[t << 2]) =
        make_float4(e0 * inv, e1 * inv, e2 * inv, e3 * inv);
}

// ---------------- 6) out = P @ V  -> g_o (token-major, heads concatenated) -----
__global__ __launch_bounds__(256) void k_pv()
{
    const int bh = blockIdx.y;
    const int m0 = blockIdx.x * 64;
    const float* A = g_attn + ((size_t)bh << 20);  // 1024x1024
    const float* B = g_v    + ((size_t)bh << 16);  // 1024x64
    float acc[4][4] = {};
    gemm64_core(A, NTOK, B, DH, NTOK, m0, 0, acc);

    const int tx = threadIdx.x & 15;
    const int ty = threadIdx.x >> 4;
    const int head = bh % NHEAD;
    const int b    = bh / NHEAD;

    #pragma unroll
    for (int i = 0; i < 4; ++i) {
        const int tok = m0 + (ty << 2) + i;
        float4 v4 = make_float4(acc[i][0], acc[i][1], acc[i][2], acc[i][3]);
        *reinterpret_cast<float4*>(
            &g_o[(size_t)(b * NTOK + tok) * HID + head * DH + (tx << 2)]) = v4;
    }
}

// ---------------- 7) final projection: d_out = g_o @ w_out + b_out -------------
__global__ __launch_bounds__(256) void k_out(
    const float* __restrict__ w, const float* __restrict__ bias,
    float* __restrict__ out)
{
    const int m0 = blockIdx.y * 64;
    const int n0 = blockIdx.x * 64;
    float acc[4][4] = {};
    gemm64_core(g_o, HID, w, HID, HID, m0, n0, acc);

    const int tx = threadIdx.x & 15;
    const int ty = threadIdx.x >> 4;
    const int col0 = n0 + (tx << 2);
    float4 bb = *reinterpret_cast<const float4*>(&bias[col0]);

    #pragma unroll
    for (int i = 0; i < 4; ++i) {
        const int m = m0 + (ty << 2) + i;
        float4 v4 = make_float4(acc[i][0] + bb.x, acc[i][1] + bb.y,
                                acc[i][2] + bb.z, acc[i][3] + bb.w);
        *reinterpret_cast<float4*>(&out[(size_t)m * HID + col0]) = v4;
    }
}

// ---------------- launcher ------------------------------------------------------
extern "C" void kernel_launch(void* const* d_in, const int* in_sizes, int n_in,
                              void* d_out, int out_size)
{
    const float* x         = (const float*)d_in[0];   // (4,32,32,768)
    const float* w_qkv     = (const float*)d_in[1];   // (768, 2304)
    const float* w_out     = (const float*)d_in[2];   // (768, 768)
    const float* b_out     = (const float*)d_in[3];   // (768,)
    const float* rel_pos_h = (const float*)d_in[4];   // (63, 64)
    const float* rel_pos_w = (const float*)d_in[5];   // (63, 64)
    float* out = (float*)d_out;                       // (4,1024,768)

    k_gemm_qkv<<<dim3(36, 64), 256>>>(x, w_qkv);
    k_transpose<<<dim3(32, 2, BH), dim3(32, 8)>>>();
    k_rel<<<dim3(NTOK, BH), 64>>>(rel_pos_h, rel_pos_w);
    k_logits<<<dim3(16, 16, BH), 256>>>();
    k_softmax<<<BH * NTOK, 256>>>();
    k_pv<<<dim3(16, BH), 256>>>();
    k_out<<<dim3(12, 64), 256>>>(w_out, b_out, out);
}

// round 2
// speedup vs baseline: 1.0982x; 1.0982x over previous
#include <cuda_runtime.h>
#include <cstdint>
#include <cstddef>

// Problem constants
#define BATCH   4
#define NHEAD   12
#define DH      64
#define HID     768
#define HDIM    32
#define WDIM    32
#define NTOK    1024
#define BH      48
#define MTOK    4096

#define BM 128
#define BN 64
#define BK 16

// ---------------- scratch (device globals) ----------------
__device__ float g_q   [(size_t)BH * NTOK * DH];
__device__ float g_k   [(size_t)BH * NTOK * DH];
__device__ float g_kT  [(size_t)BH * DH * NTOK];
__device__ float g_v   [(size_t)BH * NTOK * DH];
__device__ float g_relh[(size_t)BH * NTOK * 32];
__device__ float g_relw[(size_t)BH * NTOK * 32];
__device__ float g_attn[(size_t)BH * NTOK * NTOK];
__device__ float g_o   [(size_t)MTOK * HID];

// ---------------- f32x2 packed helpers ----------------
#define FMA2(d, a, b) \
    asm("fma.rn.f32x2 %0, %1, %2, %0;" : "+l"(d) : "l"(a), "l"(b))
#define PACK2(d, x, y) \
    asm("mov.b64 %0, {%1, %2};" : "=l"(d) : "r"(__float_as_uint(x)), "r"(__float_as_uint(y)))
#define UNPACK2(x, y, d) do {                                   \
    unsigned _lo, _hi;                                          \
    asm("mov.b64 {%0, %1}, %2;" : "=r"(_lo), "=r"(_hi) : "l"(d)); \
    x = __uint_as_float(_lo); y = __uint_as_float(_hi); } while (0)

// ---------------- 128x64x16 GEMM core, 256 threads, 8x4 micro, FFMA2 ----------
// acc[ip][j] packs rows (2ip, 2ip+1) of the 8-row micro-tile, column j.
__device__ __forceinline__ void gemm128_core(
    const float* __restrict__ A, int lda,
    const float* __restrict__ B, int ldb,
    int K, int m0, int n0, unsigned long long acc[4][4])
{
    __shared__ __align__(16) float As[BK][BM + 4];   // [k][m]
    __shared__ __align__(16) float Bs[BK][BN + 4];   // [k][n]

    const int tid = threadIdx.x;
    const int tx  = tid & 15;            // col group (4 cols)
    const int ty  = tid >> 4;            // row group (8 rows)

    const int ra  = tid >> 1;            // A row 0..127
    const int ka  = (tid & 1) << 3;      // A k-offset 0 or 8
    const int krb = tid >> 4;            // B k-row 0..15
    const int qb  = (tid & 15) << 2;     // B col chunk

    const float* pa = A + (size_t)(m0 + ra) * lda + ka;
    const float* pb = B + (size_t)krb * ldb + n0 + qb;

    // stage first tile in registers
    float4 va0 = *reinterpret_cast<const float4*>(pa);
    float4 va1 = *reinterpret_cast<const float4*>(pa + 4);
    float4 vb  = *reinterpret_cast<const float4*>(pb);

    for (int k0 = 0; k0 < K; k0 += BK) {
        As[ka + 0][ra] = va0.x; As[ka + 1][ra] = va0.y;
        As[ka + 2][ra] = va0.z; As[ka + 3][ra] = va0.w;
        As[ka + 4][ra] = va1.x; As[ka + 5][ra] = va1.y;
        As[ka + 6][ra] = va1.z; As[ka + 7][ra] = va1.w;
        *reinterpret_cast<float4*>(&Bs[krb][qb]) = vb;
        __syncthreads();

        const int kn = k0 + BK;
        if (kn < K) {                     // prefetch next tile
            va0 = *reinterpret_cast<const float4*>(pa + kn);
            va1 = *reinterpret_cast<const float4*>(pa + kn + 4);
            vb  = *reinterpret_cast<const float4*>(pb + (size_t)kn * ldb);
        }

        #pragma unroll
        for (int kk = 0; kk < BK; ++kk) {
            const ulonglong2* ap =
                reinterpret_cast<const ulonglong2*>(&As[kk][ty << 3]);
            ulonglong2 aa = ap[0];
            ulonglong2 ab = ap[1];
            unsigned long long apair[4] = {aa.x, aa.y, ab.x, ab.y};
            float4 b4 = *reinterpret_cast<const float4*>(&Bs[kk][tx << 2]);
            unsigned long long bp[4];
            PACK2(bp[0], b4.x, b4.x);
            PACK2(bp[1], b4.y, b4.y);
            PACK2(bp[2], b4.z, b4.z);
            PACK2(bp[3], b4.w, b4.w);
            #pragma unroll
            for (int ip = 0; ip < 4; ++ip)
                #pragma unroll
                for (int j = 0; j < 4; ++j)
                    FMA2(acc[ip][j], apair[ip], bp[j]);
        }
        __syncthreads();
    }
}

// unpack acc[4][4] (packed row pairs) into r[8][4]
__device__ __forceinline__ void unpack_acc(
    const unsigned long long acc[4][4], float r[8][4])
{
    #pragma unroll
    for (int ip = 0; ip < 4; ++ip)
        #pragma unroll
        for (int j = 0; j < 4; ++j)
            UNPACK2(r[2 * ip][j], r[2 * ip + 1][j], acc[ip][j]);
}

// ---------------- 1) qkv = x @ w_qkv, scatter to g_q/g_k/g_v ----------------
__global__ __launch_bounds__(256) void k_gemm_qkv(
    const float* __restrict__ x, const float* __restrict__ w)
{
    const int m0 = blockIdx.y * BM;
    const int n0 = blockIdx.x * BN;
    unsigned long long acc[4][4] = {};
    gemm128_core(x, HID, w, 3 * NHEAD * DH, HID, m0, n0, acc);
    float r[8][4];
    unpack_acc(acc, r);

    const int tx = threadIdx.x & 15;
    const int ty = threadIdx.x >> 4;
    const int sel  = n0 / (NHEAD * DH);
    const int head = (n0 % (NHEAD * DH)) >> 6;
    float* dst = (sel == 0) ? g_q : (sel == 1) ? g_k : g_v;

    #pragma unroll
    for (int rr = 0; rr < 8; ++rr) {
        const int m = m0 + (ty << 3) + rr;
        const int b = m >> 10;
        const int tok = m & 1023;
        float4 v4 = make_float4(r[rr][0], r[rr][1], r[rr][2], r[rr][3]);
        *reinterpret_cast<float4*>(
            &dst[(((size_t)(b * NHEAD + head) * NTOK + tok) << 6) + (tx << 2)]) = v4;
    }
}

// ---------------- 2) transpose K ----------------
__global__ __launch_bounds__(256) void k_transpose()
{
    __shared__ float t[32][33];
    const int bh   = blockIdx.z;
    const int tok0 = blockIdx.x * 32;
    const int d0   = blockIdx.y * 32;
    const int x  = threadIdx.x;
    const int y0 = threadIdx.y;
    const float* src = g_k  + ((size_t)bh << 16);
    float*       dst = g_kT + ((size_t)bh << 16);
    #pragma unroll
    for (int yy = 0; yy < 32; yy += 8)
        t[y0 + yy][x] = src[(size_t)(tok0 + y0 + yy) * DH + d0 + x];
    __syncthreads();
    #pragma unroll
    for (int yy = 0; yy < 32; yy += 8)
        dst[(size_t)(d0 + y0 + yy) * NTOK + tok0 + x] = t[x][y0 + yy];
}

// ---------------- 3) rel_h / rel_w tables ----------------
__global__ __launch_bounds__(64) void k_rel(
    const float* __restrict__ rel_pos_h, const float* __restrict__ rel_pos_w)
{
    const int bh  = blockIdx.y;
    const int tok = blockIdx.x;
    __shared__ float qs[64];
    const int t = threadIdx.x;
    qs[t] = g_q[(((size_t)bh << 10) + tok) * DH + t];
    __syncthreads();

    const int qh = tok >> 5;
    const int qw = tok & 31;
    const float* rp;
    float* out;
    int ridx;
    if (t < 32) {
        rp = rel_pos_h; ridx = qh - t + (HDIM - 1);
        out = &g_relh[(((size_t)bh << 10) + tok) * 32 + t];
    } else {
        const int kw = t - 32;
        rp = rel_pos_w; ridx = qw - kw + (WDIM - 1);
        out = &g_relw[(((size_t)bh << 10) + tok) * 32 + kw];
    }
    const float* rr = rp + (size_t)ridx * DH;
    float s = 0.f;
    #pragma unroll
    for (int c = 0; c < 64; ++c) s = fmaf(qs[c], rr[c], s);
    *out = s;
}

// ---------------- 4) logits = scale*Q@K^T + rel_h + rel_w ----------------
__global__ __launch_bounds__(256) void k_logits()
{
    const int bh = blockIdx.z;
    const int m0 = blockIdx.y * BM;
    const int n0 = blockIdx.x * BN;
    const float* A = g_q  + ((size_t)bh << 16);
    const float* B = g_kT + ((size_t)bh << 16);
    unsigned long long acc[4][4] = {};
    gemm128_core(A, DH, B, NTOK, DH, m0, n0, acc);
    float r[8][4];
    unpack_acc(acc, r);

    const int tx = threadIdx.x & 15;
    const int ty = threadIdx.x >> 4;
    const float scale = 0.125f;
    const int col0 = n0 + (tx << 2);
    const int kh   = col0 >> 5;
    const int kw0  = col0 & 31;
    float* outb = g_attn + ((size_t)bh << 20);

    #pragma unroll
    for (int rr = 0; rr < 8; ++rr) {
        const int tok = m0 + (ty << 3) + rr;
        const float* rh = g_relh + (((size_t)bh << 10) + tok) * 32;
        const float* rw = g_relw + (((size_t)bh << 10) + tok) * 32;
        const float bias = rh[kh];
        float4 v;
        v.x = fmaf(r[rr][0], scale, bias + rw[kw0 + 0]);
        v.y = fmaf(r[rr][1], scale, bias + rw[kw0 + 1]);
        v.z = fmaf(r[rr][2], scale, bias + rw[kw0 + 2]);
        v.w = fmaf(r[rr][3], scale, bias + rw[kw0 + 3]);
        *reinterpret_cast<float4*>(&outb[(size_t)tok * NTOK + col0]) = v;
    }
}

// ---------------- 5) softmax ----------------
__global__ __launch_bounds__(256) void k_softmax()
{
    const size_t row = blockIdx.x;
    float* p = g_attn + (row << 10);
    const int t = threadIdx.x;
    float4 v = *reinterpret_cast<const float4*>(&p[t << 2]);

    float m = fmaxf(fmaxf(v.x, v.y), fmaxf(v.z, v.w));
    #pragma unroll
    for (int o = 16; o > 0; o >>= 1)
        m = fmaxf(m, __shfl_xor_sync(0xffffffffu, m, o));

    __shared__ float smax[8];
    __shared__ float ssum[8];
    const int w = t >> 5, lane = t & 31;
    if (lane == 0) smax[w] = m;
    __syncthreads();
    float M = smax[0];
    #pragma unroll
    for (int k = 1; k < 8; ++k) M = fmaxf(M, smax[k]);

    float e0 = __expf(v.x - M);
    float e1 = __expf(v.y - M);
    float e2 = __expf(v.z - M);
    float e3 = __expf(v.w - M);
    float s = e0 + e1 + e2 + e3;
    #pragma unroll
    for (int o = 16; o > 0; o >>= 1)
        s += __shfl_xor_sync(0xffffffffu, s, o);
    if (lane == 0) ssum[w] = s;
    __syncthreads();
    float S = ssum[0];
    #pragma unroll
    for (int k = 1; k < 8; ++k) S += ssum[k];
    const float inv = 1.0f / S;

    *reinterpret_cast<float4*>(&p[t << 2]) =
        make_float4(e0 * inv, e1 * inv, e2 * inv, e3 * inv);
}

// ---------------- 6) out = P @ V -> g_o ----------------
__global__ __launch_bounds__(256) void k_pv()
{
    const int bh = blockIdx.y;
    const int m0 = blockIdx.x * BM;
    const float* A = g_attn + ((size_t)bh << 20);
    const float* B = g_v    + ((size_t)bh << 16);
    unsigned long long acc[4][4] = {};
    gemm128_core(A, NTOK, B, DH, NTOK, m0, 0, acc);
    float r[8][4];
    unpack_acc(acc, r);

    const int tx = threadIdx.x & 15;
    const int ty = threadIdx.x >> 4;
    const int head = bh % NHEAD;
    const int b    = bh / NHEAD;

    #pragma unroll
    for (int rr = 0; rr < 8; ++rr) {
        const int tok = m0 + (ty << 3) + rr;
        float4 v4 = make_float4(r[rr][0], r[rr][1], r[rr][2], r[rr][3]);
        *reinterpret_cast<float4*>(
            &g_o[(size_t)(b * NTOK + tok) * HID + head * DH + (tx << 2)]) = v4;
    }
}

// ---------------- 7) final projection ----------------
__global__ __launch_bounds__(256) void k_out(
    const float* __restrict__ w, const float* __restrict__ bias,
    float* __restrict__ out)
{
    const int m0 = blockIdx.y * BM;
    const int n0 = blockIdx.x * BN;
    unsigned long long acc[4][4] = {};
    gemm128_core(g_o, HID, w, HID, HID, m0, n0, acc);
    float r[8][4];
    unpack_acc(acc, r);

    const int tx = threadIdx.x & 15;
    const int ty = threadIdx.x >> 4;
    const int col0 = n0 + (tx << 2);
    float4 bb = *reinterpret_cast<const float4*>(&bias[col0]);

    #pragma unroll
    for (int rr = 0; rr < 8; ++rr) {
        const int m = m0 + (ty << 3) + rr;
        float4 v4 = make_float4(r[rr][0] + bb.x, r[rr][1] + bb.y,
                                r[rr][2] + bb.z, r[rr][3] + bb.w);
        *reinterpret_cast<float4*>(&out[(size_t)m * HID + col0]) = v4;
    }
}

// ---------------- launcher ----------------
extern "C" void kernel_launch(void* const* d_in, const int* in_sizes, int n_in,
                              void* d_out, int out_size)
{
    const float* x         = (const float*)d_in[0];
    const float* w_qkv     = (const float*)d_in[1];
    const float* w_out     = (const float*)d_in[2];
    const float* b_out     = (const float*)d_in[3];
    const float* rel_pos_h = (const float*)d_in[4];
    const float* rel_pos_w = (const float*)d_in[5];
    float* out = (float*)d_out;

    k_gemm_qkv<<<dim3(36, 32), 256>>>(x, w_qkv);
    k_transpose<<<dim3(32, 2, BH), dim3(32, 8)>>>();
    k_rel<<<dim3(NTOK, BH), 64>>>(rel_pos_h, rel_pos_w);
    k_logits<<<dim3(16, 8, BH), 256>>>();
    k_softmax<<<BH * NTOK, 256>>>();
    k_pv<<<dim3(8, BH), 256>>>();
    k_out<<<dim3(12, 32), 256>>>(w_out, b_out, out);
}